// round 11
// baseline (speedup 1.0000x reference)
#include <cuda_runtime.h>
#include <cuda_fp16.h>
#include <math.h>

#define NN 100000
#define NE 1600000
#define HEADS 4
#define OUT_DIM 32
#define EDGE_DIM 32
#define N_ETYPES 8
#define NEG_SLOPE 0.2f
#define SCAN_CHUNK 1024
#define NBLK ((NN + SCAN_CHUNK - 1) / SCAN_CHUNK)   // 98

typedef unsigned long long ull;

// ---------------- scratch (static device globals; no allocation) ----------------
__device__ __align__(16) __half g_embh[(size_t)NN * 128]; // [n][d*4+hd], fp16
__device__ __align__(16) float g_hl[NN * 4];
__device__ __align__(16) float g_hr[NN * 4];
__device__ __align__(16) float g_he[N_ETYPES * 4];
__device__ __align__(16) int   g_cnt[NN];
__device__ __align__(16) int   g_starts[NN + 1];
__device__ __align__(16) int   g_cursor[NN];
__device__ __align__(16) int4  g_eord[NE];   // AoS: {src, half2(x01), half2(x23), pad}
__device__ __align__(16) int   g_bsum[NBLK];
__device__ __align__(16) int   g_boff[NBLK];

__device__ __forceinline__ float lrelu(float x) { return x > 0.f ? x : NEG_SLOPE * x; }

__device__ __forceinline__ ull pk2(float lo, float hi) {
    ull r; asm("mov.b64 %0,{%1,%2};" : "=l"(r) : "f"(lo), "f"(hi)); return r;
}
__device__ __forceinline__ void upk2(ull v, float& lo, float& hi) {
    asm("mov.b64 {%0,%1},%2;" : "=f"(lo), "=f"(hi) : "l"(v));
}
__device__ __forceinline__ void fma2(ull& d, ull a, ull b) {
    asm("fma.rn.f32x2 %0,%1,%2,%0;" : "+l"(d) : "l"(a), "l"(b));
}
__device__ __forceinline__ float2 h2f(unsigned u) {
    return __half22float2(*(__half2*)&u);
}

// ---------------- kernels ----------------
// merged: zero degree histogram + typed edge-emb attention scalars (block 0)
__global__ void k_setup(const float* __restrict__ edge_emb,
                        const float* __restrict__ Wr,
                        const float* __restrict__ a_e) {
    int i = blockIdx.x * blockDim.x + threadIdx.x;
    if (i < NN) g_cnt[i] = 0;
    if (blockIdx.x == 0 && threadIdx.x < 32) {
        int tid = threadIdx.x;
        int t = tid >> 2, hh = tid & 3;
        float he = 0.f;
        for (int d = 0; d < EDGE_DIM; d++) {
            float ty = 0.f;
            const float* wr = Wr + (size_t)t * EDGE_DIM * 128 + hh * 32 + d;
            #pragma unroll 8
            for (int e = 0; e < EDGE_DIM; e++)
                ty = fmaf(edge_emb[t * EDGE_DIM + e], wr[(size_t)e * 128], ty);
            he = fmaf(a_e[hh * 32 + d], ty, he);
        }
        g_he[t * 4 + hh] = he;
    }
}

// node projection via packed f32x2 FMA, 256 threads (2 warps/SMSP):
// emb = h@W (fp16 [n][d*4+hd], staged in smem for coalesced stores),
// out init = h@res_w + res_b, plus per-node attention scalars h_l, h_r (fp32).
__global__ void __launch_bounds__(256) k_node(
    const float* __restrict__ h, const float* __restrict__ W,
    const float* __restrict__ Rw, const float* __restrict__ a_l,
    const float* __restrict__ a_r, const float* __restrict__ res_b,
    float* __restrict__ out) {
    extern __shared__ float sm[];
    float* sW = sm;                      // 128*128
    float* sR = sm + 16384;              // 128*128
    float* sh = sm + 32768;              // transposed h tile: [k][j], stride 36
    __half* sst = (__half*)(sm + 37376); // emb staging: 32 nodes * 128 halves (8KB)
    int tid = threadIdx.x;
    int col = tid & 127, g = tid >> 7;   // g in {0,1}: node half
    for (int i = tid; i < 16384; i += 256) { sW[i] = W[i]; sR[i] = Rw[i]; }
    float rl = a_l[col], rr = a_r[col], rb = res_b[col];
    int hh = col >> 5, d = col & 31, lane = tid & 31;
    __syncthreads();

    for (int base = blockIdx.x * 32; base < NN; base += gridDim.x * 32) {
        #pragma unroll
        for (int jj = 0; jj < 16; jj++) {
            int j = g * 16 + jj;
            sh[col * 36 + j] = h[(size_t)(base + j) * 128 + col];
        }
        __syncthreads();
        ull aW[8], aR[8];
        #pragma unroll
        for (int p = 0; p < 8; p++) { aW[p] = 0ull; aR[p] = 0ull; }
        #pragma unroll 4
        for (int k = 0; k < 128; k++) {
            float w = sW[k * 128 + col], r = sR[k * 128 + col];
            ull w2 = pk2(w, w), r2 = pk2(r, r);
            const ulonglong2* hp = (const ulonglong2*)&sh[k * 36 + g * 16];
            #pragma unroll
            for (int m = 0; m < 4; m++) {
                ulonglong2 u = hp[m];
                fma2(aW[2 * m],     u.x, w2);
                fma2(aW[2 * m + 1], u.y, w2);
                fma2(aR[2 * m],     u.x, r2);
                fma2(aR[2 * m + 1], u.y, r2);
            }
        }
        #pragma unroll
        for (int p = 0; p < 8; p++) {
            float e0, e1, r0v, r1v;
            upk2(aW[p], e0, e1);
            upk2(aR[p], r0v, r1v);
            int j0 = g * 16 + 2 * p;
            int n0 = base + j0, n1 = n0 + 1;
            out[(size_t)n0 * 128 + col] = r0v + rb;
            out[(size_t)n1 * 128 + col] = r1v + rb;
            sst[j0 * 128 + d * 4 + hh]       = __float2half(e0);
            sst[(j0 + 1) * 128 + d * 4 + hh] = __float2half(e1);
            float pl0 = rl * e0, pr0 = rr * e0, pl1 = rl * e1, pr1 = rr * e1;
            #pragma unroll
            for (int o = 16; o; o >>= 1) {
                pl0 += __shfl_xor_sync(0xffffffffu, pl0, o);
                pr0 += __shfl_xor_sync(0xffffffffu, pr0, o);
                pl1 += __shfl_xor_sync(0xffffffffu, pl1, o);
                pr1 += __shfl_xor_sync(0xffffffffu, pr1, o);
            }
            if (lane == 0) {
                g_hl[n0 * 4 + hh] = pl0; g_hr[n0 * 4 + hh] = pr0;
                g_hl[n1 * 4 + hh] = pl1; g_hr[n1 * 4 + hh] = pr1;
            }
        }
        __syncthreads();
        // coalesced emb store: 32 nodes * 256B = 512 x 16B
        {
            const uint4* src = (const uint4*)sst;
            uint4* dst = (uint4*)&g_embh[(size_t)base * 128];
            dst[tid] = src[tid];
            dst[tid + 256] = src[tid + 256];
        }
        __syncthreads();
    }
}

// destination-degree histogram only (logits recomputed in k_scatter)
__global__ void k_hist(const int* __restrict__ col) {
    int i = blockIdx.x * blockDim.x + threadIdx.x;   // i < NE/4
    if (i >= NE / 4) return;
    int4 c4 = ((const int4*)col)[i];
    atomicAdd(&g_cnt[c4.x], 1);
    atomicAdd(&g_cnt[c4.y], 1);
    atomicAdd(&g_cnt[c4.z], 1);
    atomicAdd(&g_cnt[c4.w], 1);
}

// parallel scan phase 1: per-block (1024-count chunk) reduction -> g_bsum
__global__ void __launch_bounds__(256) k_part() {
    __shared__ int ws[8];
    int b = blockIdx.x, tid = threadIdx.x;
    int idx = b * SCAN_CHUNK + tid * 4;
    int v = 0;
    if (idx + 3 < NN) {
        int4 t4 = *(const int4*)&g_cnt[idx];
        v = t4.x + t4.y + t4.z + t4.w;
    } else {
        #pragma unroll
        for (int q = 0; q < 4; q++) if (idx + q < NN) v += g_cnt[idx + q];
    }
    #pragma unroll
    for (int o = 16; o; o >>= 1) v += __shfl_xor_sync(0xffffffffu, v, o);
    if ((tid & 31) == 0) ws[tid >> 5] = v;
    __syncthreads();
    if (tid < 8) {
        int s = ws[tid];
        #pragma unroll
        for (int o = 4; o; o >>= 1) s += __shfl_xor_sync(0xffu, s, o);
        if (tid == 0) g_bsum[b] = s;
    }
}

// parallel scan phase 2: exclusive scan of NBLK block sums (single tiny block)
__global__ void __launch_bounds__(128) k_bscan() {
    __shared__ int ws[4];
    int tid = threadIdx.x, lane = tid & 31, wid = tid >> 5;
    int v = (tid < NBLK) ? g_bsum[tid] : 0;
    int sc = v;
    #pragma unroll
    for (int o = 1; o < 32; o <<= 1) {
        int u = __shfl_up_sync(0xffffffffu, sc, o);
        if (lane >= o) sc += u;
    }
    if (lane == 31) ws[wid] = sc;
    __syncthreads();
    int wo = 0;
    #pragma unroll
    for (int q = 0; q < 4; q++) if (q < wid) wo += ws[q];
    if (tid < NBLK) g_boff[tid] = wo + sc - v;
    if (tid == NBLK - 1) g_starts[NN] = wo + sc;
}

// parallel scan phase 3: local exclusive scan per chunk + block offset -> starts/cursor
__global__ void __launch_bounds__(256) k_csr() {
    __shared__ int ws[8];
    int b = blockIdx.x, tid = threadIdx.x, lane = tid & 31, wid = tid >> 5;
    int idx = b * SCAN_CHUNK + tid * 4;
    int v0 = 0, v1 = 0, v2 = 0, v3 = 0;
    if (idx + 3 < NN) {
        int4 t4 = *(const int4*)&g_cnt[idx];
        v0 = t4.x; v1 = t4.y; v2 = t4.z; v3 = t4.w;
    } else {
        if (idx < NN)     v0 = g_cnt[idx];
        if (idx + 1 < NN) v1 = g_cnt[idx + 1];
        if (idx + 2 < NN) v2 = g_cnt[idx + 2];
        if (idx + 3 < NN) v3 = g_cnt[idx + 3];
    }
    int tsum = v0 + v1 + v2 + v3;
    int sc = tsum;
    #pragma unroll
    for (int o = 1; o < 32; o <<= 1) {
        int u = __shfl_up_sync(0xffffffffu, sc, o);
        if (lane >= o) sc += u;
    }
    if (lane == 31) ws[wid] = sc;
    __syncthreads();
    int wo = 0;
    #pragma unroll
    for (int q = 0; q < 8; q++) if (q < wid) wo += ws[q];
    int excl = g_boff[b] + wo + sc - tsum;
    if (idx < NN)     { g_starts[idx] = excl;           g_cursor[idx] = excl; }
    if (idx + 1 < NN) { int e1 = excl + v0;             g_starts[idx + 1] = e1; g_cursor[idx + 1] = e1; }
    if (idx + 2 < NN) { int e2 = excl + v0 + v1;        g_starts[idx + 2] = e2; g_cursor[idx + 2] = e2; }
    if (idx + 3 < NN) { int e3 = excl + v0 + v1 + v2;   g_starts[idx + 3] = e3; g_cursor[idx + 3] = e3; }
}

// fused: compute exp(leaky_relu(logit)) per edge, scatter AoS record into CSR order
__global__ void k_scatter(const int* __restrict__ row, const int* __restrict__ col,
                          const int* __restrict__ et) {
    int e = blockIdx.x * blockDim.x + threadIdx.x;
    int r = row[e], c = col[e], t = et[e];
    float4 hl = *(const float4*)&g_hl[r * 4];
    float4 hr = *(const float4*)&g_hr[c * 4];
    float4 he = *(const float4*)&g_he[t * 4];
    float ex0 = __expf(lrelu(hl.x + hr.x + he.x));
    float ex1 = __expf(lrelu(hl.y + hr.y + he.y));
    float ex2 = __expf(lrelu(hl.z + hr.z + he.z));
    float ex3 = __expf(lrelu(hl.w + hr.w + he.w));
    __half2 p01 = __floats2half2_rn(ex0, ex1);
    __half2 p23 = __floats2half2_rn(ex2, ex3);
    int pos = atomicAdd(&g_cursor[c], 1);
    int4 v;
    v.x = r;
    v.y = *(int*)&p01;
    v.z = *(int*)&p23;
    v.w = 0;
    g_eord[pos] = v;
}

// atomic-free aggregation: one warp per destination node, single pass over all
// 4 heads (emb fp16 [n][d*4+hd], lane=d, uint2 = 4 heads). One LDG.128 per edge
// record + one LDG.64 emb gather. Fused normalize + residual + ELU.
__global__ void __launch_bounds__(256) k_agg(float* __restrict__ out) {
    int n = blockIdx.x * 8 + (threadIdx.x >> 5);
    int lane = threadIdx.x & 31;
    int s = g_starts[n], t = g_starts[n + 1];
    float4 acc = {0.f, 0.f, 0.f, 0.f};
    float4 den = {0.f, 0.f, 0.f, 0.f};
    int j = s;
    for (; j + 4 <= t; j += 4) {
        int4 q0 = g_eord[j], q1 = g_eord[j + 1], q2 = g_eord[j + 2], q3 = g_eord[j + 3];
        uint2 u0 = *(const uint2*)&g_embh[(size_t)q0.x * 128 + lane * 4];
        uint2 u1 = *(const uint2*)&g_embh[(size_t)q1.x * 128 + lane * 4];
        uint2 u2 = *(const uint2*)&g_embh[(size_t)q2.x * 128 + lane * 4];
        uint2 u3 = *(const uint2*)&g_embh[(size_t)q3.x * 128 + lane * 4];
        float2 x0a = h2f(q0.y), x0b = h2f(q0.z);
        float2 x1a = h2f(q1.y), x1b = h2f(q1.z);
        float2 x2a = h2f(q2.y), x2b = h2f(q2.z);
        float2 x3a = h2f(q3.y), x3b = h2f(q3.z);
        float2 a01 = h2f(u0.x), a23 = h2f(u0.y);
        float2 b01 = h2f(u1.x), b23 = h2f(u1.y);
        float2 c01 = h2f(u2.x), c23 = h2f(u2.y);
        float2 d01 = h2f(u3.x), d23 = h2f(u3.y);
        den.x += x0a.x + x1a.x + x2a.x + x3a.x;
        den.y += x0a.y + x1a.y + x2a.y + x3a.y;
        den.z += x0b.x + x1b.x + x2b.x + x3b.x;
        den.w += x0b.y + x1b.y + x2b.y + x3b.y;
        acc.x = fmaf(x0a.x, a01.x, acc.x); acc.x = fmaf(x1a.x, b01.x, acc.x);
        acc.x = fmaf(x2a.x, c01.x, acc.x); acc.x = fmaf(x3a.x, d01.x, acc.x);
        acc.y = fmaf(x0a.y, a01.y, acc.y); acc.y = fmaf(x1a.y, b01.y, acc.y);
        acc.y = fmaf(x2a.y, c01.y, acc.y); acc.y = fmaf(x3a.y, d01.y, acc.y);
        acc.z = fmaf(x0b.x, a23.x, acc.z); acc.z = fmaf(x1b.x, b23.x, acc.z);
        acc.z = fmaf(x2b.x, c23.x, acc.z); acc.z = fmaf(x3b.x, d23.x, acc.z);
        acc.w = fmaf(x0b.y, a23.y, acc.w); acc.w = fmaf(x1b.y, b23.y, acc.w);
        acc.w = fmaf(x2b.y, c23.y, acc.w); acc.w = fmaf(x3b.y, d23.y, acc.w);
    }
    for (; j < t; j++) {
        int4 q0 = g_eord[j];
        uint2 u0 = *(const uint2*)&g_embh[(size_t)q0.x * 128 + lane * 4];
        float2 x0a = h2f(q0.y), x0b = h2f(q0.z);
        float2 a01 = h2f(u0.x), a23 = h2f(u0.y);
        den.x += x0a.x; den.y += x0a.y; den.z += x0b.x; den.w += x0b.y;
        acc.x = fmaf(x0a.x, a01.x, acc.x);
        acc.y = fmaf(x0a.y, a01.y, acc.y);
        acc.z = fmaf(x0b.x, a23.x, acc.z);
        acc.w = fmaf(x0b.y, a23.y, acc.w);
    }
    float ix = (t > s) ? __frcp_rn(den.x) : 0.f;
    float iy = (t > s) ? __frcp_rn(den.y) : 0.f;
    float iz = (t > s) ? __frcp_rn(den.z) : 0.f;
    float iw = (t > s) ? __frcp_rn(den.w) : 0.f;
    float4 o = *(const float4*)&out[(size_t)n * 128 + lane * 4];
    o.x = fmaf(acc.x, ix, o.x); o.y = fmaf(acc.y, iy, o.y);
    o.z = fmaf(acc.z, iz, o.z); o.w = fmaf(acc.w, iw, o.w);
    o.x = o.x > 0.f ? o.x : expm1f(o.x);
    o.y = o.y > 0.f ? o.y : expm1f(o.y);
    o.z = o.z > 0.f ? o.z : expm1f(o.z);
    o.w = o.w > 0.f ? o.w : expm1f(o.w);
    *(float4*)&out[(size_t)n * 128 + lane * 4] = o;
}

// ---------------- launch ----------------
extern "C" void kernel_launch(void* const* d_in, const int* in_sizes, int n_in,
                              void* d_out, int out_size) {
    const float* h        = (const float*)d_in[0];
    const int*   row      = (const int*)d_in[1];
    const int*   col      = (const int*)d_in[2];
    const int*   et       = (const int*)d_in[3];
    const float* edge_emb = (const float*)d_in[4];
    const float* W        = (const float*)d_in[5];
    const float* Wr       = (const float*)d_in[6];
    const float* a_l      = (const float*)d_in[7];
    const float* a_r      = (const float*)d_in[8];
    const float* a_e      = (const float*)d_in[9];
    const float* res_w    = (const float*)d_in[10];
    const float* res_b    = (const float*)d_in[11];
    float* out = (float*)d_out;

    int nsm = 148;
    cudaDeviceGetAttribute(&nsm, cudaDevAttrMultiProcessorCount, 0);
    const int SMEM = (16384 * 2 + 128 * 36) * (int)sizeof(float) + 8192;  // 157696
    cudaFuncSetAttribute(k_node, cudaFuncAttributeMaxDynamicSharedMemorySize, SMEM);

    k_setup  <<<(NN + 255) / 256, 256>>>(edge_emb, Wr, a_e);
    k_node   <<<nsm, 256, SMEM>>>(h, W, res_w, a_l, a_r, res_b, out);
    k_hist   <<<(NE / 4 + 255) / 256, 256>>>(col);
    k_part   <<<NBLK, 256>>>();
    k_bscan  <<<1, 128>>>();
    k_csr    <<<NBLK, 256>>>();
    k_scatter<<<NE / 256, 256>>>(row, col, et);
    k_agg    <<<NN / 8, 256>>>(out);
}

// round 12
// speedup vs baseline: 1.0183x; 1.0183x over previous
#include <cuda_runtime.h>
#include <cuda_fp16.h>
#include <math.h>

#define NN 100000
#define NE 1600000
#define HEADS 4
#define OUT_DIM 32
#define EDGE_DIM 32
#define N_ETYPES 8
#define NEG_SLOPE 0.2f
#define SCAN_CHUNK 1024
#define NBLK ((NN + SCAN_CHUNK - 1) / SCAN_CHUNK)   // 98

typedef unsigned long long ull;

// ---------------- scratch (static device globals; no allocation) ----------------
__device__ __align__(16) __half g_embh[(size_t)NN * 128]; // [n][d*4+hd], fp16
__device__ __align__(16) float g_hl[NN * 4];
__device__ __align__(16) float g_hr[NN * 4];
__device__ __align__(16) float g_he[N_ETYPES * 4];
__device__ __align__(16) int   g_cnt[NN];
__device__ __align__(16) int   g_starts[NN + 1];
__device__ __align__(16) int   g_cursor[NN];
__device__ __align__(16) int4  g_eord[NE];   // AoS: {src, half2(x01), half2(x23), pad}
__device__ __align__(16) int   g_bsum[NBLK];
__device__ int g_arrive;

__device__ __forceinline__ float lrelu(float x) { return x > 0.f ? x : NEG_SLOPE * x; }

__device__ __forceinline__ ull pk2(float lo, float hi) {
    ull r; asm("mov.b64 %0,{%1,%2};" : "=l"(r) : "f"(lo), "f"(hi)); return r;
}
__device__ __forceinline__ void upk2(ull v, float& lo, float& hi) {
    asm("mov.b64 {%0,%1},%2;" : "=f"(lo), "=f"(hi) : "l"(v));
}
__device__ __forceinline__ void fma2(ull& d, ull a, ull b) {
    asm("fma.rn.f32x2 %0,%1,%2,%0;" : "+l"(d) : "l"(a), "l"(b));
}
__device__ __forceinline__ float2 h2f(unsigned u) {
    return __half22float2(*(__half2*)&u);
}

// ---------------- kernels ----------------
// merged: zero degree histogram + arrive flag + typed edge-emb attention scalars
__global__ void k_setup(const float* __restrict__ edge_emb,
                        const float* __restrict__ Wr,
                        const float* __restrict__ a_e) {
    int i = blockIdx.x * blockDim.x + threadIdx.x;
    if (i < NN) g_cnt[i] = 0;
    if (i == 0) g_arrive = 0;
    if (blockIdx.x == 0 && threadIdx.x < 32) {
        int tid = threadIdx.x;
        int t = tid >> 2, hh = tid & 3;
        float he = 0.f;
        for (int d = 0; d < EDGE_DIM; d++) {
            float ty = 0.f;
            const float* wr = Wr + (size_t)t * EDGE_DIM * 128 + hh * 32 + d;
            #pragma unroll 8
            for (int e = 0; e < EDGE_DIM; e++)
                ty = fmaf(edge_emb[t * EDGE_DIM + e], wr[(size_t)e * 128], ty);
            he = fmaf(a_e[hh * 32 + d], ty, he);
        }
        g_he[t * 4 + hh] = he;
    }
}

// node projection via packed f32x2 FMA, 256 threads (2 warps/SMSP):
// emb = h@W (fp16 [n][d*4+hd], staged in smem for coalesced stores),
// out init = h@res_w + res_b, plus per-node attention scalars h_l, h_r (fp32).
__global__ void __launch_bounds__(256) k_node(
    const float* __restrict__ h, const float* __restrict__ W,
    const float* __restrict__ Rw, const float* __restrict__ a_l,
    const float* __restrict__ a_r, const float* __restrict__ res_b,
    float* __restrict__ out) {
    extern __shared__ float sm[];
    float* sW = sm;                      // 128*128
    float* sR = sm + 16384;              // 128*128
    float* sh = sm + 32768;              // transposed h tile: [k][j], stride 36
    __half* sst = (__half*)(sm + 37376); // emb staging: 32 nodes * 128 halves (8KB)
    int tid = threadIdx.x;
    int col = tid & 127, g = tid >> 7;   // g in {0,1}: node half
    for (int i = tid; i < 16384; i += 256) { sW[i] = W[i]; sR[i] = Rw[i]; }
    float rl = a_l[col], rr = a_r[col], rb = res_b[col];
    int hh = col >> 5, d = col & 31, lane = tid & 31;
    __syncthreads();

    for (int base = blockIdx.x * 32; base < NN; base += gridDim.x * 32) {
        #pragma unroll
        for (int jj = 0; jj < 16; jj++) {
            int j = g * 16 + jj;
            sh[col * 36 + j] = h[(size_t)(base + j) * 128 + col];
        }
        __syncthreads();
        ull aW[8], aR[8];
        #pragma unroll
        for (int p = 0; p < 8; p++) { aW[p] = 0ull; aR[p] = 0ull; }
        #pragma unroll 4
        for (int k = 0; k < 128; k++) {
            float w = sW[k * 128 + col], r = sR[k * 128 + col];
            ull w2 = pk2(w, w), r2 = pk2(r, r);
            const ulonglong2* hp = (const ulonglong2*)&sh[k * 36 + g * 16];
            #pragma unroll
            for (int m = 0; m < 4; m++) {
                ulonglong2 u = hp[m];
                fma2(aW[2 * m],     u.x, w2);
                fma2(aW[2 * m + 1], u.y, w2);
                fma2(aR[2 * m],     u.x, r2);
                fma2(aR[2 * m + 1], u.y, r2);
            }
        }
        #pragma unroll
        for (int p = 0; p < 8; p++) {
            float e0, e1, r0v, r1v;
            upk2(aW[p], e0, e1);
            upk2(aR[p], r0v, r1v);
            int j0 = g * 16 + 2 * p;
            int n0 = base + j0, n1 = n0 + 1;
            out[(size_t)n0 * 128 + col] = r0v + rb;
            out[(size_t)n1 * 128 + col] = r1v + rb;
            sst[j0 * 128 + d * 4 + hh]       = __float2half(e0);
            sst[(j0 + 1) * 128 + d * 4 + hh] = __float2half(e1);
            float pl0 = rl * e0, pr0 = rr * e0, pl1 = rl * e1, pr1 = rr * e1;
            #pragma unroll
            for (int o = 16; o; o >>= 1) {
                pl0 += __shfl_xor_sync(0xffffffffu, pl0, o);
                pr0 += __shfl_xor_sync(0xffffffffu, pr0, o);
                pl1 += __shfl_xor_sync(0xffffffffu, pl1, o);
                pr1 += __shfl_xor_sync(0xffffffffu, pr1, o);
            }
            if (lane == 0) {
                g_hl[n0 * 4 + hh] = pl0; g_hr[n0 * 4 + hh] = pr0;
                g_hl[n1 * 4 + hh] = pl1; g_hr[n1 * 4 + hh] = pr1;
            }
        }
        __syncthreads();
        // coalesced emb store: 32 nodes * 256B = 512 x 16B
        {
            const uint4* src = (const uint4*)sst;
            uint4* dst = (uint4*)&g_embh[(size_t)base * 128];
            dst[tid] = src[tid];
            dst[tid + 256] = src[tid + 256];
        }
        __syncthreads();
    }
}

// destination-degree histogram only (logits recomputed in k_scatter)
__global__ void k_hist(const int* __restrict__ col) {
    int i = blockIdx.x * blockDim.x + threadIdx.x;   // i < NE/4
    if (i >= NE / 4) return;
    int4 c4 = __ldcs((const int4*)col + i);
    atomicAdd(&g_cnt[c4.x], 1);
    atomicAdd(&g_cnt[c4.y], 1);
    atomicAdd(&g_cnt[c4.z], 1);
    atomicAdd(&g_cnt[c4.w], 1);
}

// single-kernel scan: 98 co-resident blocks, global release/acquire barrier.
// phase 1: local scan + block sum -> g_bsum; phase 2: cross-block prefix -> starts/cursor
__global__ void __launch_bounds__(256) k_scan1() {
    __shared__ int ws[8];
    __shared__ int s_boff;
    int b = blockIdx.x, tid = threadIdx.x, lane = tid & 31, wid = tid >> 5;
    int idx = b * SCAN_CHUNK + tid * 4;
    int v0 = 0, v1 = 0, v2 = 0, v3 = 0;
    if (idx + 3 < NN) {
        int4 t4 = *(const int4*)&g_cnt[idx];
        v0 = t4.x; v1 = t4.y; v2 = t4.z; v3 = t4.w;
    } else {
        if (idx < NN)     v0 = g_cnt[idx];
        if (idx + 1 < NN) v1 = g_cnt[idx + 1];
        if (idx + 2 < NN) v2 = g_cnt[idx + 2];
        if (idx + 3 < NN) v3 = g_cnt[idx + 3];
    }
    int tsum = v0 + v1 + v2 + v3;
    // local inclusive warp scan
    int sc = tsum;
    #pragma unroll
    for (int o = 1; o < 32; o <<= 1) {
        int u = __shfl_up_sync(0xffffffffu, sc, o);
        if (lane >= o) sc += u;
    }
    if (lane == 31) ws[wid] = sc;
    __syncthreads();
    int wo = 0;
    #pragma unroll
    for (int q = 0; q < 8; q++) if (q < wid) wo += ws[q];
    int btot = 0;
    #pragma unroll
    for (int q = 0; q < 8; q++) btot += ws[q];
    __syncthreads();           // everyone done reading ws before reuse
    // publish block sum, arrive
    if (tid == 0) {
        g_bsum[b] = btot;
        __threadfence();
        atomicAdd(&g_arrive, 1);
    }
    // wait for all blocks
    if (tid == 0) {
        int a;
        do {
            asm volatile("ld.acquire.gpu.global.b32 %0, [%1];" : "=r"(a) : "l"(&g_arrive) : "memory");
            if (a >= NBLK) break;
            __nanosleep(64);
        } while (true);
    }
    __syncthreads();
    // cross-block exclusive prefix: sum of g_bsum[q < b]
    int pv = (tid < b) ? g_bsum[tid] : 0;     // NBLK=98 < 256 threads
    #pragma unroll
    for (int o = 16; o; o >>= 1) pv += __shfl_xor_sync(0xffffffffu, pv, o);
    if (lane == 0) ws[wid] = pv;
    __syncthreads();
    if (tid == 0) {
        int sum = 0;
        #pragma unroll
        for (int q = 0; q < 8; q++) sum += ws[q];
        s_boff = sum;
        if (b == NBLK - 1) g_starts[NN] = sum + btot;
    }
    __syncthreads();
    int excl = s_boff + wo + sc - tsum;
    if (idx < NN)     { g_starts[idx] = excl;           g_cursor[idx] = excl; }
    if (idx + 1 < NN) { int e1 = excl + v0;             g_starts[idx + 1] = e1; g_cursor[idx + 1] = e1; }
    if (idx + 2 < NN) { int e2 = excl + v0 + v1;        g_starts[idx + 2] = e2; g_cursor[idx + 2] = e2; }
    if (idx + 3 < NN) { int e3 = excl + v0 + v1 + v2;   g_starts[idx + 3] = e3; g_cursor[idx + 3] = e3; }
}

// fused: compute exp(leaky_relu(logit)) per edge, scatter AoS record into CSR order
__global__ void k_scatter(const int* __restrict__ row, const int* __restrict__ col,
                          const int* __restrict__ et) {
    int e = blockIdx.x * blockDim.x + threadIdx.x;
    int r = __ldcs(&row[e]), c = __ldcs(&col[e]), t = __ldcs(&et[e]);
    float4 hl = *(const float4*)&g_hl[r * 4];
    float4 hr = *(const float4*)&g_hr[c * 4];
    float4 he = *(const float4*)&g_he[t * 4];
    float ex0 = __expf(lrelu(hl.x + hr.x + he.x));
    float ex1 = __expf(lrelu(hl.y + hr.y + he.y));
    float ex2 = __expf(lrelu(hl.z + hr.z + he.z));
    float ex3 = __expf(lrelu(hl.w + hr.w + he.w));
    __half2 p01 = __floats2half2_rn(ex0, ex1);
    __half2 p23 = __floats2half2_rn(ex2, ex3);
    int pos = atomicAdd(&g_cursor[c], 1);
    int4 v;
    v.x = r;
    v.y = *(int*)&p01;
    v.z = *(int*)&p23;
    v.w = 0;
    __stcs(&g_eord[pos], v);
}

// atomic-free aggregation: one warp per destination node, 8-edge-wide iterations
// for MLP, fp16 emb gathers (L2-resident), fused normalize + residual + ELU.
__global__ void __launch_bounds__(256) k_agg(float* __restrict__ out) {
    int n = blockIdx.x * 8 + (threadIdx.x >> 5);
    int lane = threadIdx.x & 31;
    int s = g_starts[n], t = g_starts[n + 1];
    float4 acc = {0.f, 0.f, 0.f, 0.f};
    float4 den = {0.f, 0.f, 0.f, 0.f};
    int j = s;
    for (; j + 8 <= t; j += 8) {
        int4 q[8];
        uint2 u[8];
        #pragma unroll
        for (int m = 0; m < 8; m++) q[m] = __ldcs(&g_eord[j + m]);
        #pragma unroll
        for (int m = 0; m < 8; m++)
            u[m] = *(const uint2*)&g_embh[(size_t)q[m].x * 128 + lane * 4];
        #pragma unroll
        for (int m = 0; m < 8; m++) {
            float2 xa = h2f(q[m].y), xb = h2f(q[m].z);
            float2 e01 = h2f(u[m].x), e23 = h2f(u[m].y);
            den.x += xa.x; den.y += xa.y; den.z += xb.x; den.w += xb.y;
            acc.x = fmaf(xa.x, e01.x, acc.x);
            acc.y = fmaf(xa.y, e01.y, acc.y);
            acc.z = fmaf(xb.x, e23.x, acc.z);
            acc.w = fmaf(xb.y, e23.y, acc.w);
        }
    }
    for (; j < t; j++) {
        int4 q0 = __ldcs(&g_eord[j]);
        uint2 u0 = *(const uint2*)&g_embh[(size_t)q0.x * 128 + lane * 4];
        float2 xa = h2f(q0.y), xb = h2f(q0.z);
        float2 e01 = h2f(u0.x), e23 = h2f(u0.y);
        den.x += xa.x; den.y += xa.y; den.z += xb.x; den.w += xb.y;
        acc.x = fmaf(xa.x, e01.x, acc.x);
        acc.y = fmaf(xa.y, e01.y, acc.y);
        acc.z = fmaf(xb.x, e23.x, acc.z);
        acc.w = fmaf(xb.y, e23.y, acc.w);
    }
    float ix = (t > s) ? __frcp_rn(den.x) : 0.f;
    float iy = (t > s) ? __frcp_rn(den.y) : 0.f;
    float iz = (t > s) ? __frcp_rn(den.z) : 0.f;
    float iw = (t > s) ? __frcp_rn(den.w) : 0.f;
    float4 o = *(const float4*)&out[(size_t)n * 128 + lane * 4];
    o.x = fmaf(acc.x, ix, o.x); o.y = fmaf(acc.y, iy, o.y);
    o.z = fmaf(acc.z, iz, o.z); o.w = fmaf(acc.w, iw, o.w);
    o.x = o.x > 0.f ? o.x : expm1f(o.x);
    o.y = o.y > 0.f ? o.y : expm1f(o.y);
    o.z = o.z > 0.f ? o.z : expm1f(o.z);
    o.w = o.w > 0.f ? o.w : expm1f(o.w);
    *(float4*)&out[(size_t)n * 128 + lane * 4] = o;
}

// ---------------- launch ----------------
extern "C" void kernel_launch(void* const* d_in, const int* in_sizes, int n_in,
                              void* d_out, int out_size) {
    const float* h        = (const float*)d_in[0];
    const int*   row      = (const int*)d_in[1];
    const int*   col      = (const int*)d_in[2];
    const int*   et       = (const int*)d_in[3];
    const float* edge_emb = (const float*)d_in[4];
    const float* W        = (const float*)d_in[5];
    const float* Wr       = (const float*)d_in[6];
    const float* a_l      = (const float*)d_in[7];
    const float* a_r      = (const float*)d_in[8];
    const float* a_e      = (const float*)d_in[9];
    const float* res_w    = (const float*)d_in[10];
    const float* res_b    = (const float*)d_in[11];
    float* out = (float*)d_out;

    int nsm = 148;
    cudaDeviceGetAttribute(&nsm, cudaDevAttrMultiProcessorCount, 0);
    const int SMEM = (16384 * 2 + 128 * 36) * (int)sizeof(float) + 8192;  // 157696
    cudaFuncSetAttribute(k_node, cudaFuncAttributeMaxDynamicSharedMemorySize, SMEM);

    k_setup  <<<(NN + 255) / 256, 256>>>(edge_emb, Wr, a_e);
    k_node   <<<nsm, 256, SMEM>>>(h, W, res_w, a_l, a_r, res_b, out);
    k_hist   <<<(NE / 4 + 255) / 256, 256>>>(col);
    k_scan1  <<<NBLK, 256>>>();
    k_scatter<<<NE / 256, 256>>>(row, col, et);
    k_agg    <<<NN / 8, 256>>>(out);
}